// round 2
// baseline (speedup 1.0000x reference)
#include <cuda_runtime.h>
#include <cstdint>
#include <math.h>

#define H 2048
#define NBOP 8
#define MAXA 10

// ---------------- device state ----------------
__device__ __align__(16) float g_h[2][H];
__device__ __align__(16) float g_c[H];
__device__ __align__(16) float g_x[H];
__device__ __align__(16) float g_anchors[MAXA][H];
__device__ __align__(16) float g_aw1[MAXA][H];
__device__ __align__(16) float g_r[H];
__device__ uint32_t g_key[2];
__device__ float g_lp;
__device__ float g_ent;
__device__ float g_arc[64];

// ---------------- threefry2x32 (20 rounds) ----------------
__device__ __forceinline__ uint32_t rotl32(uint32_t v, int d) {
    return (v << d) | (v >> (32 - d));
}

__device__ __forceinline__ void tf2x32(uint32_t k0, uint32_t k1,
                                       uint32_t x0, uint32_t x1,
                                       uint32_t& y0, uint32_t& y1) {
    uint32_t ks0 = k0, ks1 = k1, ks2 = 0x1BD11BDAu ^ k0 ^ k1;
    x0 += ks0; x1 += ks1;
#define TF_RND(r) { x0 += x1; x1 = rotl32(x1, r); x1 ^= x0; }
    TF_RND(13) TF_RND(15) TF_RND(26) TF_RND(6)
    x0 += ks1; x1 += ks2 + 1u;
    TF_RND(17) TF_RND(29) TF_RND(16) TF_RND(24)
    x0 += ks2; x1 += ks0 + 2u;
    TF_RND(13) TF_RND(15) TF_RND(26) TF_RND(6)
    x0 += ks0; x1 += ks1 + 3u;
    TF_RND(17) TF_RND(29) TF_RND(16) TF_RND(24)
    x0 += ks1; x1 += ks2 + 4u;
    TF_RND(13) TF_RND(15) TF_RND(26) TF_RND(6)
    x0 += ks2; x1 += ks0 + 5u;
#undef TF_RND
    y0 = x0; y1 = x1;
}

__device__ __forceinline__ float sigf(float z) { return 1.0f / (1.0f + expf(-z)); }

// JAX partitionable PRNG semantics:
//   split(key):  keys[i] = threefry(key, (0, i))  -> key=keys[0], sub=keys[1]
//   bits(sub,n): bits[i] = y0 ^ y1 of threefry(sub, (0, i))
// Gumbel-max categorical + log_softmax accumulators. Runs in one thread.
__device__ int d_sample(const float* L, int n) {
    uint32_t k0 = g_key[0], k1 = g_key[1];
    uint32_t nk0, nk1, sk0, sk1;
    tf2x32(k0, k1, 0u, 0u, nk0, nk1);
    tf2x32(k0, k1, 0u, 1u, sk0, sk1);
    g_key[0] = nk0; g_key[1] = nk1;

    float best = 0.0f; int idx = 0;
    for (int i = 0; i < n; i++) {
        uint32_t b0, b1;
        tf2x32(sk0, sk1, 0u, (uint32_t)i, b0, b1);
        uint32_t bits = b0 ^ b1;
        float f = __uint_as_float((bits >> 9) | 0x3f800000u) - 1.0f;
        float u = (f > 0.0f) ? f : 1.17549435e-38f;
        float z = L[i] - logf(-logf(u));
        if (i == 0 || z > best) { best = z; idx = i; }
    }
    // log_softmax on L
    float m = L[0];
    for (int i = 1; i < n; i++) m = fmaxf(m, L[i]);
    float se = 0.0f;
    for (int i = 0; i < n; i++) se += expf(L[i] - m);
    float lse = m + logf(se);
    float ent = 0.0f;
    for (int i = 0; i < n; i++) { float l = L[i] - lse; ent -= l * expf(l); }
    g_lp  += -(L[idx] - lse);
    g_ent += ent;
    return idx;
}

// ---------------- init kernels ----------------
__global__ void k_init() {
    int i = blockIdx.x * blockDim.x + threadIdx.x;
    if (i < H) { g_h[0][i] = 0.0f; g_h[1][i] = 0.0f; g_c[i] = 0.0f; }
    if (i == 0) {
        g_key[0] = 0u; g_key[1] = 42u;   // jax.random.key(42)
        g_lp = 0.0f; g_ent = 0.0f;
    }
}

__global__ void k_sampler_init(const float* __restrict__ enc) {
    int i = blockIdx.x * blockDim.x + threadIdx.x;
    if (i < H) {
        g_x[i] = enc[i];          // inputs = encoder_w[0]
        g_anchors[0][i] = 0.0f;   // anchors[0..1] = zeros
        g_anchors[1][i] = 0.0f;
    }
}

// ---------------- fused LSTM cell ----------------
// Block j computes all 4 gate dots for output element j, then the gate math.
__global__ __launch_bounds__(256) void k_cell(
    const float* __restrict__ w_ih, const float* __restrict__ b_ih,
    const float* __restrict__ w_hh, const float* __restrict__ b_hh, int par) {
    const int j = blockIdx.x, t = threadIdx.x;
    const float4* __restrict__ x4 = (const float4*)g_x;
    const float4* __restrict__ h4 = (const float4*)g_h[par];
    const float4* wi0 = (const float4*)(w_ih + (size_t)(0 * H + j) * H);
    const float4* wi1 = (const float4*)(w_ih + (size_t)(1 * H + j) * H);
    const float4* wi2 = (const float4*)(w_ih + (size_t)(2 * H + j) * H);
    const float4* wi3 = (const float4*)(w_ih + (size_t)(3 * H + j) * H);
    const float4* wh0 = (const float4*)(w_hh + (size_t)(0 * H + j) * H);
    const float4* wh1 = (const float4*)(w_hh + (size_t)(1 * H + j) * H);
    const float4* wh2 = (const float4*)(w_hh + (size_t)(2 * H + j) * H);
    const float4* wh3 = (const float4*)(w_hh + (size_t)(3 * H + j) * H);

    float s0 = 0.f, s1 = 0.f, s2 = 0.f, s3 = 0.f;
    for (int k = t; k < H / 4; k += 256) {
        float4 xv = x4[k], hv = h4[k];
        float4 a;
        a = wi0[k]; s0 += a.x * xv.x + a.y * xv.y + a.z * xv.z + a.w * xv.w;
        a = wh0[k]; s0 += a.x * hv.x + a.y * hv.y + a.z * hv.z + a.w * hv.w;
        a = wi1[k]; s1 += a.x * xv.x + a.y * xv.y + a.z * xv.z + a.w * xv.w;
        a = wh1[k]; s1 += a.x * hv.x + a.y * hv.y + a.z * hv.z + a.w * hv.w;
        a = wi2[k]; s2 += a.x * xv.x + a.y * xv.y + a.z * xv.z + a.w * xv.w;
        a = wh2[k]; s2 += a.x * hv.x + a.y * hv.y + a.z * hv.z + a.w * hv.w;
        a = wi3[k]; s3 += a.x * xv.x + a.y * xv.y + a.z * xv.z + a.w * xv.w;
        a = wh3[k]; s3 += a.x * hv.x + a.y * hv.y + a.z * hv.z + a.w * hv.w;
    }
    // warp reduce
    for (int o = 16; o > 0; o >>= 1) {
        s0 += __shfl_down_sync(0xffffffffu, s0, o);
        s1 += __shfl_down_sync(0xffffffffu, s1, o);
        s2 += __shfl_down_sync(0xffffffffu, s2, o);
        s3 += __shfl_down_sync(0xffffffffu, s3, o);
    }
    __shared__ float sb[8][4];
    if ((t & 31) == 0) {
        sb[t >> 5][0] = s0; sb[t >> 5][1] = s1; sb[t >> 5][2] = s2; sb[t >> 5][3] = s3;
    }
    __syncthreads();
    if (t == 0) {
        float r0 = 0.f, r1 = 0.f, r2 = 0.f, r3 = 0.f;
        for (int w = 0; w < 8; w++) {
            r0 += sb[w][0]; r1 += sb[w][1]; r2 += sb[w][2]; r3 += sb[w][3];
        }
        float gi = sigf(r0 + b_ih[0 * H + j] + b_hh[0 * H + j]);
        float gf = sigf(r1 + b_ih[1 * H + j] + b_hh[1 * H + j]);
        float gg = tanhf(r2 + b_ih[2 * H + j] + b_hh[2 * H + j]);
        float go = sigf(r3 + b_ih[3 * H + j] + b_hh[3 * H + j]);
        float c2 = gf * g_c[j] + gi * gg;
        g_c[j] = c2;
        g_h[par ^ 1][j] = go * tanhf(c2);
    }
}

// ---------------- generic reduce helper for 128-thread GEMV ----------------
__device__ __forceinline__ float dot_h_row(const float4* __restrict__ wr,
                                           const float4* __restrict__ h4, int t) {
    float s = 0.f;
    for (int k = t; k < H / 4; k += 128) {
        float4 a = wr[k], hv = h4[k];
        s += a.x * hv.x + a.y * hv.y + a.z * hv.z + a.w * hv.w;
    }
    for (int o = 16; o > 0; o >>= 1) s += __shfl_down_sync(0xffffffffu, s, o);
    __shared__ float sb[4];
    if ((t & 31) == 0) sb[t >> 5] = s;
    __syncthreads();
    return sb[0] + sb[1] + sb[2] + sb[3];
}

// g_r = h @ W2^T
__global__ __launch_bounds__(128) void k_gemv_r(const float* __restrict__ W2, int par) {
    int m = blockIdx.x, t = threadIdx.x;
    float s = dot_h_row((const float4*)(W2 + (size_t)m * H), (const float4*)g_h[par], t);
    if (t == 0) g_r[m] = s;
}

// g_aw1[a] = h @ W1^T ; optionally record anchor (h) and reset x = encoder_w[0]
__global__ __launch_bounds__(128) void k_w1row(const float* __restrict__ W1,
                                               const float* __restrict__ enc,
                                               int a, int par, int record) {
    int m = blockIdx.x, t = threadIdx.x;
    float s = dot_h_row((const float4*)(W1 + (size_t)m * H), (const float4*)g_h[par], t);
    if (t == 0) {
        g_aw1[a][m] = s;
        if (record) {
            g_anchors[a][m] = g_h[par][m];
            g_x[m] = enc[m];   // inputs = encoder_w[0:1]
        }
    }
}

// ---------------- attention logits + sample + gather (1 block) ----------------
__global__ __launch_bounds__(256) void k_attn(const float* __restrict__ v,
                                              int n, int slot, int par) {
    const int t = threadIdx.x;
    __shared__ float red[256];
    __shared__ float sl[MAXA];
    __shared__ int s_idx;
    float part[MAXA];
    for (int l = 0; l < n; l++) part[l] = 0.f;
    for (int k = t; k < H; k += 256) {
        float rv = g_r[k], vv = v[k];
        for (int l = 0; l < n; l++)
            part[l] += vv * tanhf(g_aw1[l][k] + rv);
    }
    for (int l = 0; l < n; l++) {
        red[t] = part[l];
        __syncthreads();
        for (int o = 128; o > 0; o >>= 1) {
            if (t < o) red[t] += red[t + o];
            __syncthreads();
        }
        if (t == 0) sl[l] = red[0];
        __syncthreads();
    }
    if (t == 0) {
        float L[MAXA];
        for (int l = 0; l < n; l++) L[l] = 2.5f * tanhf(sl[l] / 5.0f);
        int idx = d_sample(L, n);
        g_arc[slot] = (float)idx;
        s_idx = idx;
    }
    __syncthreads();
    int idx = s_idx;
    for (int k = t; k < H; k += 256) g_x[k] = g_anchors[idx][k];
}

// ---------------- op logits + sample + gather (1 block) ----------------
__global__ __launch_bounds__(256) void k_op(const float* __restrict__ w_soft,
                                            const float* __restrict__ b_soft,
                                            const float* __restrict__ b_nl,
                                            const float* __restrict__ enc,
                                            int use_bias, int slot, int par) {
    const int t = threadIdx.x;
    __shared__ float red[256];
    __shared__ float sl[NBOP];
    __shared__ int s_op;
    const float* __restrict__ h = g_h[par];
    float part[NBOP];
    for (int o = 0; o < NBOP; o++) part[o] = 0.f;
    for (int k = t; k < H; k += 256) {
        float hv = h[k];
        for (int o = 0; o < NBOP; o++)
            part[o] += w_soft[(size_t)o * H + k] * hv;
    }
    for (int o = 0; o < NBOP; o++) {
        red[t] = part[o];
        __syncthreads();
        for (int s = 128; s > 0; s >>= 1) {
            if (t < s) red[t] += red[t + s];
            __syncthreads();
        }
        if (t == 0) sl[o] = red[0];
        __syncthreads();
    }
    if (t == 0) {
        float L[NBOP];
        for (int o = 0; o < NBOP; o++) {
            L[o] = (2.5f / 2.5f) * tanhf((sl[o] + b_soft[o]) / 5.0f);
            if (use_bias) L[o] += b_nl[o];
        }
        int op = d_sample(L, NBOP);
        g_arc[slot] = (float)op;
        s_op = op;
    }
    __syncthreads();
    int op = s_op;
    const float* __restrict__ src = enc + (size_t)(op + 1) * H;
    for (int k = t; k < H; k += 256) g_x[k] = src[k];
}

// ---------------- finalize ----------------
__global__ void k_final(float* __restrict__ out, int out_size) {
    int t = threadIdx.x + blockIdx.x * blockDim.x;
    if (t < out_size) out[t] = 0.0f;
    if (t < 64 && t < out_size) out[t] = g_arc[t];
    if (t == 64 && t < out_size) out[t] = g_lp;
    if (t == 65 && t < out_size) out[t] = g_ent;
}

// ---------------- host schedule ----------------
extern "C" void kernel_launch(void* const* d_in, const int* in_sizes, int n_in,
                              void* d_out, int out_size) {
    const float* enc    = (const float*)d_in[0];
    const float* w_ih   = (const float*)d_in[1];
    const float* b_ih   = (const float*)d_in[2];
    const float* w_hh   = (const float*)d_in[3];
    const float* b_hh   = (const float*)d_in[4];
    const float* w_soft = (const float*)d_in[5];
    const float* b_soft = (const float*)d_in[6];
    const float* b_nl   = (const float*)d_in[7];
    const float* w1     = (const float*)d_in[8];
    const float* w2     = (const float*)d_in[9];
    const float* v      = (const float*)d_in[10];

    int par = 0;
    k_init<<<8, 256>>>();
    for (int s = 0; s < 2; s++) {
        int use_bias = (s == 0) ? 1 : 0;
        k_sampler_init<<<8, 256>>>(enc);
        for (int a = 0; a < 2; a++) {
            k_cell<<<H, 256>>>(w_ih, b_ih, w_hh, b_hh, par); par ^= 1;
            k_w1row<<<H, 128>>>(w1, enc, a, par, 0);
        }
        for (int layer = 2; layer < 10; layer++) {
            int base = s * 32 + 4 * (layer - 2);
            for (int t2 = 0; t2 < 2; t2++) {
                k_cell<<<H, 256>>>(w_ih, b_ih, w_hh, b_hh, par); par ^= 1;
                k_gemv_r<<<H, 128>>>(w2, par);
                k_attn<<<1, 256>>>(v, layer, base + (t2 ? 2 : 0), par);
            }
            for (int t2 = 0; t2 < 2; t2++) {
                k_cell<<<H, 256>>>(w_ih, b_ih, w_hh, b_hh, par); par ^= 1;
                k_op<<<1, 256>>>(w_soft, b_soft, b_nl, enc, use_bias,
                                 base + 1 + 2 * t2, par);
            }
            k_cell<<<H, 256>>>(w_ih, b_ih, w_hh, b_hh, par); par ^= 1;
            k_w1row<<<H, 128>>>(w1, enc, layer, par, 1);
        }
    }
    int nfin = (out_size + 255) / 256;
    if (nfin < 1) nfin = 1;
    k_final<<<nfin, 256>>>((float*)d_out, out_size);
}

// round 4
// speedup vs baseline: 1.7351x; 1.7351x over previous
#include <cuda_runtime.h>
#include <cuda_bf16.h>
#include <cstdint>
#include <math.h>

#define H 2048
#define NBOP 8
#define MAXA 10

// ---------------- device state ----------------
__device__ __align__(16) float g_h[2][H];
__device__ __align__(16) float g_c[H];
__device__ __align__(16) float g_x[H];
__device__ __align__(16) float g_anchors[MAXA][H];
__device__ __align__(16) float g_aw1[MAXA][H];
__device__ __align__(16) float g_r[H];
__device__ __align__(16) float g_bias[4 * H];            // b_ih + b_hh
__device__ __align__(16) __nv_bfloat16 g_wih_bf[4 * H * H];  // 33.5 MB
__device__ __align__(16) __nv_bfloat16 g_whh_bf[4 * H * H];  // 33.5 MB
__device__ uint32_t g_key[2];
__device__ float g_lp;
__device__ float g_ent;
__device__ float g_arc[64];

// ---------------- threefry2x32 (20 rounds) ----------------
__device__ __forceinline__ uint32_t rotl32(uint32_t v, int d) {
    return (v << d) | (v >> (32 - d));
}

__device__ __forceinline__ void tf2x32(uint32_t k0, uint32_t k1,
                                       uint32_t x0, uint32_t x1,
                                       uint32_t& y0, uint32_t& y1) {
    uint32_t ks0 = k0, ks1 = k1, ks2 = 0x1BD11BDAu ^ k0 ^ k1;
    x0 += ks0; x1 += ks1;
#define TF_RND(r) { x0 += x1; x1 = rotl32(x1, r); x1 ^= x0; }
    TF_RND(13) TF_RND(15) TF_RND(26) TF_RND(6)
    x0 += ks1; x1 += ks2 + 1u;
    TF_RND(17) TF_RND(29) TF_RND(16) TF_RND(24)
    x0 += ks2; x1 += ks0 + 2u;
    TF_RND(13) TF_RND(15) TF_RND(26) TF_RND(6)
    x0 += ks0; x1 += ks1 + 3u;
    TF_RND(17) TF_RND(29) TF_RND(16) TF_RND(24)
    x0 += ks1; x1 += ks2 + 4u;
    TF_RND(13) TF_RND(15) TF_RND(26) TF_RND(6)
    x0 += ks2; x1 += ks0 + 5u;
#undef TF_RND
    y0 = x0; y1 = x1;
}

__device__ __forceinline__ float sigf(float z) { return 1.0f / (1.0f + expf(-z)); }

// JAX partitionable PRNG semantics (VERIFIED round 1: rel_err 2.7e-7 — do not touch):
//   split(key):  keys[i] = threefry(key, (0, i))  -> key=keys[0], sub=keys[1]
//   bits(sub,n): bits[i] = y0 ^ y1 of threefry(sub, (0, i))
__device__ int d_sample(const float* L, int n) {
    uint32_t k0 = g_key[0], k1 = g_key[1];
    uint32_t nk0, nk1, sk0, sk1;
    tf2x32(k0, k1, 0u, 0u, nk0, nk1);
    tf2x32(k0, k1, 0u, 1u, sk0, sk1);
    g_key[0] = nk0; g_key[1] = nk1;

    float best = 0.0f; int idx = 0;
    for (int i = 0; i < n; i++) {
        uint32_t b0, b1;
        tf2x32(sk0, sk1, 0u, (uint32_t)i, b0, b1);
        uint32_t bits = b0 ^ b1;
        float f = __uint_as_float((bits >> 9) | 0x3f800000u) - 1.0f;
        float u = (f > 0.0f) ? f : 1.17549435e-38f;
        float z = L[i] - logf(-logf(u));
        if (i == 0 || z > best) { best = z; idx = i; }
    }
    float m = L[0];
    for (int i = 1; i < n; i++) m = fmaxf(m, L[i]);
    float se = 0.0f;
    for (int i = 0; i < n; i++) se += expf(L[i] - m);
    float lse = m + logf(se);
    float ent = 0.0f;
    for (int i = 0; i < n; i++) { float l = L[i] - lse; ent -= l * expf(l); }
    g_lp  += -(L[idx] - lse);
    g_ent += ent;
    return idx;
}

// ---------------- weight conversion (fp32 -> bf16) + bias fuse ----------------
__global__ __launch_bounds__(256) void k_convert(
    const float* __restrict__ w_ih, const float* __restrict__ w_hh,
    const float* __restrict__ b_ih, const float* __restrict__ b_hh) {
    const size_t n4 = (size_t)4 * H * H / 4;   // float4 count
    size_t i = (size_t)blockIdx.x * blockDim.x + threadIdx.x;
    if (i < n4) {
        float4 a = ((const float4*)w_ih)[i];
        float4 b = ((const float4*)w_hh)[i];
        __nv_bfloat162* oi = (__nv_bfloat162*)g_wih_bf;
        __nv_bfloat162* oh = (__nv_bfloat162*)g_whh_bf;
        oi[2 * i]     = __floats2bfloat162_rn(a.x, a.y);
        oi[2 * i + 1] = __floats2bfloat162_rn(a.z, a.w);
        oh[2 * i]     = __floats2bfloat162_rn(b.x, b.y);
        oh[2 * i + 1] = __floats2bfloat162_rn(b.z, b.w);
    }
    if (i < 4 * H) g_bias[i] = b_ih[i] + b_hh[i];
}

// ---------------- init kernels ----------------
__global__ void k_init() {
    int i = blockIdx.x * blockDim.x + threadIdx.x;
    if (i < H) { g_h[0][i] = 0.0f; g_h[1][i] = 0.0f; g_c[i] = 0.0f; }
    if (i == 0) {
        g_key[0] = 0u; g_key[1] = 42u;
        g_lp = 0.0f; g_ent = 0.0f;
    }
}

__global__ void k_sampler_init(const float* __restrict__ enc) {
    int i = blockIdx.x * blockDim.x + threadIdx.x;
    if (i < H) {
        g_x[i] = enc[i];
        g_anchors[0][i] = 0.0f;
        g_anchors[1][i] = 0.0f;
    }
}

// ---------------- fused LSTM cell (bf16 weights) ----------------
// Block j computes all 4 gates for output element j.
// Each row of a gate matrix is H bf16 = 4096 B = 256 uint4; thread t owns uint4 #t.
__device__ __forceinline__ float bdot8(uint4 w, float4 a, float4 b) {
    float2 f0 = __bfloat1622float2(*(__nv_bfloat162*)&w.x);
    float2 f1 = __bfloat1622float2(*(__nv_bfloat162*)&w.y);
    float2 f2 = __bfloat1622float2(*(__nv_bfloat162*)&w.z);
    float2 f3 = __bfloat1622float2(*(__nv_bfloat162*)&w.w);
    return f0.x * a.x + f0.y * a.y + f1.x * a.z + f1.y * a.w
         + f2.x * b.x + f2.y * b.y + f3.x * b.z + f3.y * b.w;
}

__global__ __launch_bounds__(256) void k_cell(int par) {
    const int j = blockIdx.x, t = threadIdx.x;
    const float4* __restrict__ x4 = (const float4*)g_x;
    const float4* __restrict__ h4 = (const float4*)g_h[par];
    float4 xa = x4[2 * t], xb = x4[2 * t + 1];
    float4 ha = h4[2 * t], hb = h4[2 * t + 1];
    const uint4* __restrict__ wi = (const uint4*)g_wih_bf;
    const uint4* __restrict__ wh = (const uint4*)g_whh_bf;

    float s0, s1, s2, s3;
    {
        uint4 a, b;
        a = wi[((size_t)(0 * H + j)) * 256 + t];
        b = wh[((size_t)(0 * H + j)) * 256 + t];
        s0 = bdot8(a, xa, xb) + bdot8(b, ha, hb);
        a = wi[((size_t)(1 * H + j)) * 256 + t];
        b = wh[((size_t)(1 * H + j)) * 256 + t];
        s1 = bdot8(a, xa, xb) + bdot8(b, ha, hb);
        a = wi[((size_t)(2 * H + j)) * 256 + t];
        b = wh[((size_t)(2 * H + j)) * 256 + t];
        s2 = bdot8(a, xa, xb) + bdot8(b, ha, hb);
        a = wi[((size_t)(3 * H + j)) * 256 + t];
        b = wh[((size_t)(3 * H + j)) * 256 + t];
        s3 = bdot8(a, xa, xb) + bdot8(b, ha, hb);
    }
    for (int o = 16; o > 0; o >>= 1) {
        s0 += __shfl_down_sync(0xffffffffu, s0, o);
        s1 += __shfl_down_sync(0xffffffffu, s1, o);
        s2 += __shfl_down_sync(0xffffffffu, s2, o);
        s3 += __shfl_down_sync(0xffffffffu, s3, o);
    }
    __shared__ float sb[8][4];
    if ((t & 31) == 0) {
        sb[t >> 5][0] = s0; sb[t >> 5][1] = s1; sb[t >> 5][2] = s2; sb[t >> 5][3] = s3;
    }
    __syncthreads();
    if (t == 0) {
        float r0 = 0.f, r1 = 0.f, r2 = 0.f, r3 = 0.f;
        for (int w = 0; w < 8; w++) {
            r0 += sb[w][0]; r1 += sb[w][1]; r2 += sb[w][2]; r3 += sb[w][3];
        }
        float gi = sigf(r0 + g_bias[0 * H + j]);
        float gf = sigf(r1 + g_bias[1 * H + j]);
        float gg = tanhf(r2 + g_bias[2 * H + j]);
        float go = sigf(r3 + g_bias[3 * H + j]);
        float c2 = gf * g_c[j] + gi * gg;
        g_c[j] = c2;
        g_h[par ^ 1][j] = go * tanhf(c2);
    }
}

// ---------------- 256-thread fp32 GEMV helper ----------------
__device__ __forceinline__ float dot_h_row256(const float4* __restrict__ wr,
                                              const float4* __restrict__ h4, int t) {
    float4 a0 = wr[t], a1 = wr[t + 256];
    float4 h0 = h4[t], h1 = h4[t + 256];
    float s = a0.x * h0.x + a0.y * h0.y + a0.z * h0.z + a0.w * h0.w
            + a1.x * h1.x + a1.y * h1.y + a1.z * h1.z + a1.w * h1.w;
    for (int o = 16; o > 0; o >>= 1) s += __shfl_down_sync(0xffffffffu, s, o);
    __shared__ float sb[8];
    if ((t & 31) == 0) sb[t >> 5] = s;
    __syncthreads();
    float r = 0.f;
    if (t == 0)
        r = sb[0] + sb[1] + sb[2] + sb[3] + sb[4] + sb[5] + sb[6] + sb[7];
    return r;
}

// g_r = h @ W2^T
__global__ __launch_bounds__(256) void k_gemv_r(const float* __restrict__ W2, int par) {
    int m = blockIdx.x, t = threadIdx.x;
    float s = dot_h_row256((const float4*)(W2 + (size_t)m * H), (const float4*)g_h[par], t);
    if (t == 0) g_r[m] = s;
}

// g_aw1[a] = h @ W1^T ; optionally record anchor (h) and reset x = encoder_w[0]
__global__ __launch_bounds__(256) void k_w1row(const float* __restrict__ W1,
                                               const float* __restrict__ enc,
                                               int a, int par, int record) {
    int m = blockIdx.x, t = threadIdx.x;
    float s = dot_h_row256((const float4*)(W1 + (size_t)m * H), (const float4*)g_h[par], t);
    if (t == 0) {
        g_aw1[a][m] = s;
        if (record) {
            g_anchors[a][m] = g_h[par][m];
            g_x[m] = enc[m];
        }
    }
}

// ---------------- attention logits + sample + gather (1 block) ----------------
__global__ __launch_bounds__(256) void k_attn(const float* __restrict__ v,
                                              int n, int slot, int par) {
    const int t = threadIdx.x;
    __shared__ float red[256];
    __shared__ float sl[MAXA];
    __shared__ int s_idx;
    float part[MAXA];
    for (int l = 0; l < n; l++) part[l] = 0.f;
    for (int k = t; k < H; k += 256) {
        float rv = g_r[k], vv = v[k];
        for (int l = 0; l < n; l++)
            part[l] += vv * tanhf(g_aw1[l][k] + rv);
    }
    for (int l = 0; l < n; l++) {
        red[t] = part[l];
        __syncthreads();
        for (int o = 128; o > 0; o >>= 1) {
            if (t < o) red[t] += red[t + o];
            __syncthreads();
        }
        if (t == 0) sl[l] = red[0];
        __syncthreads();
    }
    if (t == 0) {
        float L[MAXA];
        for (int l = 0; l < n; l++) L[l] = 2.5f * tanhf(sl[l] / 5.0f);
        int idx = d_sample(L, n);
        g_arc[slot] = (float)idx;
        s_idx = idx;
    }
    __syncthreads();
    int idx = s_idx;
    for (int k = t; k < H; k += 256) g_x[k] = g_anchors[idx][k];
}

// ---------------- op logits + sample + gather (1 block) ----------------
__global__ __launch_bounds__(256) void k_op(const float* __restrict__ w_soft,
                                            const float* __restrict__ b_soft,
                                            const float* __restrict__ b_nl,
                                            const float* __restrict__ enc,
                                            int use_bias, int slot, int par) {
    const int t = threadIdx.x;
    __shared__ float red[256];
    __shared__ float sl[NBOP];
    __shared__ int s_op;
    const float* __restrict__ h = g_h[par];
    float part[NBOP];
    for (int o = 0; o < NBOP; o++) part[o] = 0.f;
    for (int k = t; k < H; k += 256) {
        float hv = h[k];
        for (int o = 0; o < NBOP; o++)
            part[o] += w_soft[(size_t)o * H + k] * hv;
    }
    for (int o = 0; o < NBOP; o++) {
        red[t] = part[o];
        __syncthreads();
        for (int s = 128; s > 0; s >>= 1) {
            if (t < s) red[t] += red[t + s];
            __syncthreads();
        }
        if (t == 0) sl[o] = red[0];
        __syncthreads();
    }
    if (t == 0) {
        float L[NBOP];
        for (int o = 0; o < NBOP; o++) {
            L[o] = tanhf((sl[o] + b_soft[o]) / 5.0f);
            if (use_bias) L[o] += b_nl[o];
        }
        int op = d_sample(L, NBOP);
        g_arc[slot] = (float)op;
        s_op = op;
    }
    __syncthreads();
    int op = s_op;
    const float* __restrict__ src = enc + (size_t)(op + 1) * H;
    for (int k = t; k < H; k += 256) g_x[k] = src[k];
}

// ---------------- finalize ----------------
__global__ void k_final(float* __restrict__ out, int out_size) {
    int t = threadIdx.x + blockIdx.x * blockDim.x;
    if (t < out_size) out[t] = 0.0f;
    if (t < 64 && t < out_size) out[t] = g_arc[t];
    if (t == 64 && t < out_size) out[t] = g_lp;
    if (t == 65 && t < out_size) out[t] = g_ent;
}

// ---------------- host schedule ----------------
extern "C" void kernel_launch(void* const* d_in, const int* in_sizes, int n_in,
                              void* d_out, int out_size) {
    const float* enc    = (const float*)d_in[0];
    const float* w_ih   = (const float*)d_in[1];
    const float* b_ih   = (const float*)d_in[2];
    const float* w_hh   = (const float*)d_in[3];
    const float* b_hh   = (const float*)d_in[4];
    const float* w_soft = (const float*)d_in[5];
    const float* b_soft = (const float*)d_in[6];
    const float* b_nl   = (const float*)d_in[7];
    const float* w1     = (const float*)d_in[8];
    const float* w2     = (const float*)d_in[9];
    const float* v      = (const float*)d_in[10];

    {
        size_t n4 = (size_t)4 * H * H / 4;
        int blocks = (int)((n4 + 255) / 256);
        k_convert<<<blocks, 256>>>(w_ih, w_hh, b_ih, b_hh);
    }

    int par = 0;
    k_init<<<8, 256>>>();
    for (int s = 0; s < 2; s++) {
        int use_bias = (s == 0) ? 1 : 0;
        k_sampler_init<<<8, 256>>>(enc);
        for (int a = 0; a < 2; a++) {
            k_cell<<<H, 256>>>(par); par ^= 1;
            k_w1row<<<H, 256>>>(w1, enc, a, par, 0);
        }
        for (int layer = 2; layer < 10; layer++) {
            int base = s * 32 + 4 * (layer - 2);
            for (int t2 = 0; t2 < 2; t2++) {
                k_cell<<<H, 256>>>(par); par ^= 1;
                k_gemv_r<<<H, 256>>>(w2, par);
                k_attn<<<1, 256>>>(v, layer, base + (t2 ? 2 : 0), par);
            }
            for (int t2 = 0; t2 < 2; t2++) {
                k_cell<<<H, 256>>>(par); par ^= 1;
                k_op<<<1, 256>>>(w_soft, b_soft, b_nl, enc, use_bias,
                                 base + 1 + 2 * t2, par);
            }
            k_cell<<<H, 256>>>(par); par ^= 1;
            k_w1row<<<H, 256>>>(w1, enc, layer, par, 1);
        }
    }
    int nfin = (out_size + 255) / 256;
    if (nfin < 1) nfin = 1;
    k_final<<<nfin, 256>>>((float*)d_out, out_size);
}

// round 8
// speedup vs baseline: 2.0882x; 1.2035x over previous
#include <cuda_runtime.h>
#include <cuda_bf16.h>
#include <cstdint>
#include <math.h>

#define H 2048
#define NBOP 8
#define MAXA 10
#define NENC 9   // NB + 1 encoder rows

// ---------------- device state ----------------
__device__ __align__(16) float g_h[2][H];
__device__ __align__(16) float g_c[H];
__device__ __align__(16) float g_x[H];
__device__ __align__(16) float g_anchors[MAXA][H];
__device__ __align__(16) float g_aw1[MAXA][H];
__device__ __align__(16) float g_r[H];
__device__ __align__(16) float g_bias[4 * H];                 // b_ih + b_hh
__device__ __align__(16) float g_wih_enc[NENC][4 * H];        // precomputed w_ih @ enc[k]
__device__ __align__(16) __nv_bfloat16 g_wih_bf[4 * H * H];   // 33.5 MB
__device__ __align__(16) __nv_bfloat16 g_whh_bf[4 * H * H];   // 33.5 MB
__device__ __align__(16) __nv_bfloat16 g_w1_bf[H * H];        // 8.4 MB
__device__ __align__(16) __nv_bfloat16 g_w2_bf[H * H];        // 8.4 MB
__device__ int g_xrow;           // >=0: x == encoder_w[g_xrow] (use precompute); -1: dynamic x in g_x
__device__ uint32_t g_key[2];
__device__ float g_lp;
__device__ float g_ent;
__device__ float g_arc[64];

// ---------------- threefry2x32 (20 rounds) ----------------
__device__ __forceinline__ uint32_t rotl32(uint32_t v, int d) {
    return (v << d) | (v >> (32 - d));
}

__device__ __forceinline__ void tf2x32(uint32_t k0, uint32_t k1,
                                       uint32_t x0, uint32_t x1,
                                       uint32_t& y0, uint32_t& y1) {
    uint32_t ks0 = k0, ks1 = k1, ks2 = 0x1BD11BDAu ^ k0 ^ k1;
    x0 += ks0; x1 += ks1;
#define TF_RND(r) { x0 += x1; x1 = rotl32(x1, r); x1 ^= x0; }
    TF_RND(13) TF_RND(15) TF_RND(26) TF_RND(6)
    x0 += ks1; x1 += ks2 + 1u;
    TF_RND(17) TF_RND(29) TF_RND(16) TF_RND(24)
    x0 += ks2; x1 += ks0 + 2u;
    TF_RND(13) TF_RND(15) TF_RND(26) TF_RND(6)
    x0 += ks0; x1 += ks1 + 3u;
    TF_RND(17) TF_RND(29) TF_RND(16) TF_RND(24)
    x0 += ks1; x1 += ks2 + 4u;
    TF_RND(13) TF_RND(15) TF_RND(26) TF_RND(6)
    x0 += ks2; x1 += ks0 + 5u;
#undef TF_RND
    y0 = x0; y1 = x1;
}

__device__ __forceinline__ float sigf(float z) { return 1.0f / (1.0f + expf(-z)); }

// JAX partitionable PRNG semantics (VERIFIED: rel_err 2.7e-7 in fp32 run — do not touch):
//   split(key):  keys[i] = threefry(key, (0, i))  -> key=keys[0], sub=keys[1]
//   bits(sub,n): bits[i] = y0 ^ y1 of threefry(sub, (0, i))
__device__ int d_sample(const float* L, int n) {
    uint32_t k0 = g_key[0], k1 = g_key[1];
    uint32_t nk0, nk1, sk0, sk1;
    tf2x32(k0, k1, 0u, 0u, nk0, nk1);
    tf2x32(k0, k1, 0u, 1u, sk0, sk1);
    g_key[0] = nk0; g_key[1] = nk1;

    float best = 0.0f; int idx = 0;
    for (int i = 0; i < n; i++) {
        uint32_t b0, b1;
        tf2x32(sk0, sk1, 0u, (uint32_t)i, b0, b1);
        uint32_t bits = b0 ^ b1;
        float f = __uint_as_float((bits >> 9) | 0x3f800000u) - 1.0f;
        float u = (f > 0.0f) ? f : 1.17549435e-38f;
        float z = L[i] - logf(-logf(u));
        if (i == 0 || z > best) { best = z; idx = i; }
    }
    float m = L[0];
    for (int i = 1; i < n; i++) m = fmaxf(m, L[i]);
    float se = 0.0f;
    for (int i = 0; i < n; i++) se += expf(L[i] - m);
    float lse = m + logf(se);
    float ent = 0.0f;
    for (int i = 0; i < n; i++) { float l = L[i] - lse; ent -= l * expf(l); }
    g_lp  += -(L[idx] - lse);
    g_ent += ent;
    return idx;
}

// ---------------- weight conversion (fp32 -> bf16) + bias fuse ----------------
__global__ __launch_bounds__(256) void k_convert(
    const float* __restrict__ w_ih, const float* __restrict__ w_hh,
    const float* __restrict__ w1, const float* __restrict__ w2,
    const float* __restrict__ b_ih, const float* __restrict__ b_hh) {
    const size_t n4 = (size_t)4 * H * H / 4;   // float4 count for ih/hh
    const size_t m4 = (size_t)H * H / 4;       // float4 count for w1/w2
    size_t i = (size_t)blockIdx.x * blockDim.x + threadIdx.x;
    if (i < n4) {
        float4 a = ((const float4*)w_ih)[i];
        float4 b = ((const float4*)w_hh)[i];
        __nv_bfloat162* oi = (__nv_bfloat162*)g_wih_bf;
        __nv_bfloat162* oh = (__nv_bfloat162*)g_whh_bf;
        oi[2 * i]     = __floats2bfloat162_rn(a.x, a.y);
        oi[2 * i + 1] = __floats2bfloat162_rn(a.z, a.w);
        oh[2 * i]     = __floats2bfloat162_rn(b.x, b.y);
        oh[2 * i + 1] = __floats2bfloat162_rn(b.z, b.w);
    }
    if (i < m4) {
        float4 a = ((const float4*)w1)[i];
        float4 b = ((const float4*)w2)[i];
        __nv_bfloat162* o1 = (__nv_bfloat162*)g_w1_bf;
        __nv_bfloat162* o2 = (__nv_bfloat162*)g_w2_bf;
        o1[2 * i]     = __floats2bfloat162_rn(a.x, a.y);
        o1[2 * i + 1] = __floats2bfloat162_rn(a.z, a.w);
        o2[2 * i]     = __floats2bfloat162_rn(b.x, b.y);
        o2[2 * i + 1] = __floats2bfloat162_rn(b.z, b.w);
    }
    if (i < 4 * H) g_bias[i] = b_ih[i] + b_hh[i];
}

// ---------------- precompute w_ih @ enc[k]^T for all 9 encoder rows (fp32) ----------------
__global__ __launch_bounds__(256) void k_precomp(const float* __restrict__ w_ih,
                                                 const float* __restrict__ enc) {
    const int g = blockIdx.x;   // output row 0..4H-1 (= gate*H + j)
    const int t = threadIdx.x;
    const float4* __restrict__ wr = (const float4*)(w_ih + (size_t)g * H);
    float4 a0 = wr[t], a1 = wr[t + 256];
    float acc[NENC];
#pragma unroll
    for (int k = 0; k < NENC; k++) {
        const float4* __restrict__ e4 = (const float4*)(enc + (size_t)k * H);
        float4 e0 = e4[t], e1 = e4[t + 256];
        acc[k] = a0.x * e0.x + a0.y * e0.y + a0.z * e0.z + a0.w * e0.w
               + a1.x * e1.x + a1.y * e1.y + a1.z * e1.z + a1.w * e1.w;
    }
    __shared__ float sb[8][NENC];
#pragma unroll
    for (int k = 0; k < NENC; k++) {
        float s = acc[k];
        for (int o = 16; o > 0; o >>= 1) s += __shfl_down_sync(0xffffffffu, s, o);
        if ((t & 31) == 0) sb[t >> 5][k] = s;
    }
    __syncthreads();
    if (t < NENC) {
        float r = 0.f;
        for (int w = 0; w < 8; w++) r += sb[w][t];
        g_wih_enc[t][g] = r;
    }
}

// ---------------- init kernels ----------------
__global__ void k_init() {
    int i = blockIdx.x * blockDim.x + threadIdx.x;
    if (i < H) { g_h[0][i] = 0.0f; g_h[1][i] = 0.0f; g_c[i] = 0.0f; }
    if (i == 0) {
        g_key[0] = 0u; g_key[1] = 42u;
        g_lp = 0.0f; g_ent = 0.0f;
    }
}

__global__ void k_sampler_init(const float* __restrict__ enc) {
    int i = blockIdx.x * blockDim.x + threadIdx.x;
    if (i < H) {
        g_x[i] = enc[i];
        g_anchors[0][i] = 0.0f;
        g_anchors[1][i] = 0.0f;
    }
    if (i == 0) g_xrow = 0;   // inputs = encoder_w[0]
}

// ---------------- fused LSTM cell (bf16 weights, static-x fast path) ----------------
__device__ __forceinline__ float bdot8(uint4 w, float4 a, float4 b) {
    float2 f0 = __bfloat1622float2(*(__nv_bfloat162*)&w.x);
    float2 f1 = __bfloat1622float2(*(__nv_bfloat162*)&w.y);
    float2 f2 = __bfloat1622float2(*(__nv_bfloat162*)&w.z);
    float2 f3 = __bfloat1622float2(*(__nv_bfloat162*)&w.w);
    return f0.x * a.x + f0.y * a.y + f1.x * a.z + f1.y * a.w
         + f2.x * b.x + f2.y * b.y + f3.x * b.z + f3.y * b.w;
}

__global__ __launch_bounds__(256) void k_cell(int par) {
    const int j = blockIdx.x, t = threadIdx.x;
    const int xrow = g_xrow;   // uniform across grid
    const float4* __restrict__ h4 = (const float4*)g_h[par];
    float4 ha = h4[2 * t], hb = h4[2 * t + 1];
    const uint4* __restrict__ wh = (const uint4*)g_whh_bf;

    float s0, s1, s2, s3;
    if (xrow < 0) {
        const float4* __restrict__ x4 = (const float4*)g_x;
        float4 xa = x4[2 * t], xb = x4[2 * t + 1];
        const uint4* __restrict__ wi = (const uint4*)g_wih_bf;
        uint4 a, b;
        a = wi[((size_t)(0 * H + j)) * 256 + t];
        b = wh[((size_t)(0 * H + j)) * 256 + t];
        s0 = bdot8(a, xa, xb) + bdot8(b, ha, hb);
        a = wi[((size_t)(1 * H + j)) * 256 + t];
        b = wh[((size_t)(1 * H + j)) * 256 + t];
        s1 = bdot8(a, xa, xb) + bdot8(b, ha, hb);
        a = wi[((size_t)(2 * H + j)) * 256 + t];
        b = wh[((size_t)(2 * H + j)) * 256 + t];
        s2 = bdot8(a, xa, xb) + bdot8(b, ha, hb);
        a = wi[((size_t)(3 * H + j)) * 256 + t];
        b = wh[((size_t)(3 * H + j)) * 256 + t];
        s3 = bdot8(a, xa, xb) + bdot8(b, ha, hb);
    } else {
        uint4 b;
        b = wh[((size_t)(0 * H + j)) * 256 + t]; s0 = bdot8(b, ha, hb);
        b = wh[((size_t)(1 * H + j)) * 256 + t]; s1 = bdot8(b, ha, hb);
        b = wh[((size_t)(2 * H + j)) * 256 + t]; s2 = bdot8(b, ha, hb);
        b = wh[((size_t)(3 * H + j)) * 256 + t]; s3 = bdot8(b, ha, hb);
    }
    for (int o = 16; o > 0; o >>= 1) {
        s0 += __shfl_down_sync(0xffffffffu, s0, o);
        s1 += __shfl_down_sync(0xffffffffu, s1, o);
        s2 += __shfl_down_sync(0xffffffffu, s2, o);
        s3 += __shfl_down_sync(0xffffffffu, s3, o);
    }
    __shared__ float sb[8][4];
    if ((t & 31) == 0) {
        sb[t >> 5][0] = s0; sb[t >> 5][1] = s1; sb[t >> 5][2] = s2; sb[t >> 5][3] = s3;
    }
    __syncthreads();
    if (t == 0) {
        float r0 = 0.f, r1 = 0.f, r2 = 0.f, r3 = 0.f;
        for (int w = 0; w < 8; w++) {
            r0 += sb[w][0]; r1 += sb[w][1]; r2 += sb[w][2]; r3 += sb[w][3];
        }
        if (xrow >= 0) {
            r0 += g_wih_enc[xrow][0 * H + j];
            r1 += g_wih_enc[xrow][1 * H + j];
            r2 += g_wih_enc[xrow][2 * H + j];
            r3 += g_wih_enc[xrow][3 * H + j];
        }
        float gi = sigf(r0 + g_bias[0 * H + j]);
        float gf = sigf(r1 + g_bias[1 * H + j]);
        float gg = tanhf(r2 + g_bias[2 * H + j]);
        float go = sigf(r3 + g_bias[3 * H + j]);
        float c2 = gf * g_c[j] + gi * gg;
        g_c[j] = c2;
        g_h[par ^ 1][j] = go * tanhf(c2);
    }
}

// ---------------- bf16 GEMV helper (row = 256 uint4 of bf16) ----------------
__device__ __forceinline__ float bdot_row(const uint4* __restrict__ wr,
                                          const float4* __restrict__ h4, int t) {
    uint4 w = wr[t];
    float s = bdot8(w, h4[2 * t], h4[2 * t + 1]);
    for (int o = 16; o > 0; o >>= 1) s += __shfl_down_sync(0xffffffffu, s, o);
    __shared__ float sb[8];
    if ((t & 31) == 0) sb[t >> 5] = s;
    __syncthreads();
    float r = 0.f;
    if (t == 0)
        r = sb[0] + sb[1] + sb[2] + sb[3] + sb[4] + sb[5] + sb[6] + sb[7];
    return r;
}

// g_r = h @ W2^T (bf16)
__global__ __launch_bounds__(256) void k_gemv_r(int par) {
    int m = blockIdx.x, t = threadIdx.x;
    const uint4* wr = (const uint4*)(g_w2_bf + (size_t)m * H);
    float s = bdot_row(wr, (const float4*)g_h[par], t);
    if (t == 0) g_r[m] = s;
}

// g_aw1[a] = h @ W1^T (bf16); optionally record anchor and mark x = enc[0]
__global__ __launch_bounds__(256) void k_w1row(int a, int par, int record) {
    int m = blockIdx.x, t = threadIdx.x;
    const uint4* wr = (const uint4*)(g_w1_bf + (size_t)m * H);
    float s = bdot_row(wr, (const float4*)g_h[par], t);
    if (t == 0) {
        g_aw1[a][m] = s;
        if (record) {
            g_anchors[a][m] = g_h[par][m];
            if (m == 0) g_xrow = 0;   // inputs = encoder_w[0:1]
        }
    }
}

// ---------------- attention logits + sample + gather (1 block) ----------------
__global__ __launch_bounds__(256) void k_attn(const float* __restrict__ v,
                                              int n, int slot, int par) {
    const int t = threadIdx.x;
    __shared__ float red[256];
    __shared__ float sl[MAXA];
    __shared__ int s_idx;
    float part[MAXA];
    for (int l = 0; l < n; l++) part[l] = 0.f;
    for (int k = t; k < H; k += 256) {
        float rv = g_r[k], vv = v[k];
        for (int l = 0; l < n; l++)
            part[l] += vv * tanhf(g_aw1[l][k] + rv);
    }
    for (int l = 0; l < n; l++) {
        red[t] = part[l];
        __syncthreads();
        for (int o = 128; o > 0; o >>= 1) {
            if (t < o) red[t] += red[t + o];
            __syncthreads();
        }
        if (t == 0) sl[l] = red[0];
        __syncthreads();
    }
    if (t == 0) {
        float L[MAXA];
        for (int l = 0; l < n; l++) L[l] = 2.5f * tanhf(sl[l] / 5.0f);
        int idx = d_sample(L, n);
        g_arc[slot] = (float)idx;
        g_xrow = -1;      // dynamic input follows
        s_idx = idx;
    }
    __syncthreads();
    int idx = s_idx;
    for (int k = t; k < H; k += 256) g_x[k] = g_anchors[idx][k];
}

// ---------------- op logits + sample (1 block) ----------------
__global__ __launch_bounds__(256) void k_op(const float* __restrict__ w_soft,
                                            const float* __restrict__ b_soft,
                                            const float* __restrict__ b_nl,
                                            int use_bias, int slot, int par) {
    const int t = threadIdx.x;
    __shared__ float red[256];
    __shared__ float sl[NBOP];
    const float* __restrict__ h = g_h[par];
    float part[NBOP];
    for (int o = 0; o < NBOP; o++) part[o] = 0.f;
    for (int k = t; k < H; k += 256) {
        float hv = h[k];
        for (int o = 0; o < NBOP; o++)
            part[o] += w_soft[(size_t)o * H + k] * hv;
    }
    for (int o = 0; o < NBOP; o++) {
        red[t] = part[o];
        __syncthreads();
        for (int s = 128; s > 0; s >>= 1) {
            if (t < s) red[t] += red[t + s];
            __syncthreads();
        }
        if (t == 0) sl[o] = red[0];
        __syncthreads();
    }
    if (t == 0) {
        float L[NBOP];
        for (int o = 0; o < NBOP; o++) {
            L[o] = tanhf((sl[o] + b_soft[o]) / 5.0f);
            if (use_bias) L[o] += b_nl[o];
        }
        int op = d_sample(L, NBOP);
        g_arc[slot] = (float)op;
        g_xrow = op + 1;   // inputs = encoder_w[op+1] -> precomputed path
    }
}

// ---------------- finalize ----------------
__global__ void k_final(float* __restrict__ out, int out_size) {
    int t = threadIdx.x + blockIdx.x * blockDim.x;
    if (t < out_size) out[t] = 0.0f;
    if (t < 64 && t < out_size) out[t] = g_arc[t];
    if (t == 64 && t < out_size) out[t] = g_lp;
    if (t == 65 && t < out_size) out[t] = g_ent;
}

// ---------------- host schedule ----------------
extern "C" void kernel_launch(void* const* d_in, const int* in_sizes, int n_in,
                              void* d_out, int out_size) {
    const float* enc    = (const float*)d_in[0];
    const float* w_ih   = (const float*)d_in[1];
    const float* b_ih   = (const float*)d_in[2];
    const float* w_hh   = (const float*)d_in[3];
    const float* b_hh   = (const float*)d_in[4];
    const float* w_soft = (const float*)d_in[5];
    const float* b_soft = (const float*)d_in[6];
    const float* b_nl   = (const float*)d_in[7];
    const float* w1     = (const float*)d_in[8];
    const float* w2     = (const float*)d_in[9];
    const float* v      = (const float*)d_in[10];

    {
        size_t n4 = (size_t)4 * H * H / 4;
        int blocks = (int)((n4 + 255) / 256);
        k_convert<<<blocks, 256>>>(w_ih, w_hh, w1, w2, b_ih, b_hh);
    }
    k_precomp<<<4 * H, 256>>>(w_ih, enc);

    int par = 0;
    k_init<<<8, 256>>>();
    for (int s = 0; s < 2; s++) {
        int use_bias = (s == 0) ? 1 : 0;
        k_sampler_init<<<8, 256>>>(enc);
        for (int a = 0; a < 2; a++) {
            k_cell<<<H, 256>>>(par); par ^= 1;
            k_w1row<<<H, 256>>>(a, par, 0);
        }
        for (int layer = 2; layer < 10; layer++) {
            int base = s * 32 + 4 * (layer - 2);
            for (int t2 = 0; t2 < 2; t2++) {
                k_cell<<<H, 256>>>(par); par ^= 1;
                k_gemv_r<<<H, 256>>>(par);
                k_attn<<<1, 256>>>(v, layer, base + (t2 ? 2 : 0), par);
            }
            for (int t2 = 0; t2 < 2; t2++) {
                k_cell<<<H, 256>>>(par); par ^= 1;
                k_op<<<1, 256>>>(w_soft, b_soft, b_nl, use_bias,
                                 base + 1 + 2 * t2, par);
            }
            k_cell<<<H, 256>>>(par); par ^= 1;
            k_w1row<<<H, 256>>>(layer, par, 1);
        }
    }
    int nfin = (out_size + 255) / 256;
    if (nfin < 1) nfin = 1;
    k_final<<<nfin, 256>>>((float*)d_out, out_size);
}